// round 3
// baseline (speedup 1.0000x reference)
#include <cuda_runtime.h>
#include <cstdint>
#include <math.h>

// Problem constants
#define BATCH 64
#define QN    2000
#define CN    200
#define NPB   (QN*CN)        // 400000 elements per batch
#define NPB4  (NPB/4)        // 100000 float4 per batch
#define TOPK  100
#define PARTS 20             // chunks per batch -> 64*20 = 1280 blocks of 256 thr (~1 wave)
#define CH4   5000           // float4 per chunk (20*5000 = 100000 exactly)
#define GCAP  8192           // per-batch global candidate capacity
#define NBINS 2048           // k_final histogram bins = top 11 bits of flipped key
#define FBUF  2048           // final-kernel survivor buffer

// Global scratch (static device arrays: no allocation in kernel_launch)
__device__ float g_cval[(size_t)BATCH * GCAP];
__device__ int   g_cidx[(size_t)BATCH * GCAP];
__device__ int   g_cnt[BATCH];
__device__ float g_thrF[BATCH];

__device__ __forceinline__ unsigned fkey(float f) {
    unsigned u = __float_as_uint(f);
    return (u & 0x80000000u) ? ~u : (u | 0x80000000u);
}
__device__ __forceinline__ float unkey(unsigned k) {
    unsigned u = (k & 0x80000000u) ? (k ^ 0x80000000u) : ~k;
    return __uint_as_float(u);
}

// Warp-collective (threads 0..31): find max bin g such that
// sum(hist[g..NBINS-1]) >= Keff. Returns (g << 21) on all lanes.
__device__ __forceinline__ unsigned warp_find_thr(const int* hist, int Keff,
                                                  volatile int* sufArr) {
    const int lane = threadIdx.x & 31;
    int part = 0;
#pragma unroll 8
    for (int i = 0; i < 64; i++) part += hist[lane * 64 + i];
    int s = part;
#pragma unroll
    for (int off = 1; off < 32; off <<= 1) {
        int t = __shfl_down_sync(0xFFFFFFFFu, s, off);
        if (lane + off < 32) s += t;
    }
    sufArr[lane] = s;
    __syncwarp();
    unsigned thr = 0;
    if (lane == 0) {
        int c = 0;
        for (int l = 31; l >= 0; l--) {
            if (sufArr[l] >= Keff) { c = l; break; }
        }
        int running = (c < 31) ? sufArr[c + 1] : 0;
        int g = c * 64 + 63;
        for (;; --g) {
            running += hist[g];
            if (running >= Keff || g == c * 64) break;
        }
        thr = ((unsigned)g) << 21;
    }
    thr = __shfl_sync(0xFFFFFFFFu, thr, 0);
    return thr;
}

// ---------------------------------------------------------------------------
// k_thr: per-batch approximate threshold. One block per batch.
// Samples 2048 float4 (8192 values) strided across the batch; each thread
// keeps the max of its 32 samples; then a 16-step binary search over the top
// 16 key bits using __syncthreads_count finds the largest key prefix with
// >= 16 thread-maxima above it. Expected survivors ~800; P(<100) ~ 1e-9.
// Also zeroes the per-batch candidate counter.
// ---------------------------------------------------------------------------
__global__ __launch_bounds__(256)
void k_thr(const float* __restrict__ logits) {
    const int b = blockIdx.x;
    const int tid = threadIdx.x;
    const float4* lp4 = reinterpret_cast<const float4*>(logits) + (size_t)b * NPB4;

    float m = __int_as_float(0xFF800000);   // -inf
#pragma unroll
    for (int k = 0; k < 8; k++) {
        int j = tid + k * 256;              // 0..2047
        float4 a = __ldg(lp4 + (size_t)j * 48);  // 2047*48 = 98256 < 100000
        m = fmaxf(m, fmaxf(fmaxf(a.x, a.y), fmaxf(a.z, a.w)));
    }
    const unsigned key = fkey(m);
    unsigned thr = 0;
#pragma unroll
    for (int bit = 31; bit >= 16; --bit) {
        unsigned cand = thr | (1u << bit);
        int cnt = __syncthreads_count(key >= cand);
        if (cnt >= 16) thr = cand;
    }
    if (tid == 0) {
        g_thrF[b] = unkey(thr);
        g_cnt[b] = 0;
    }
}

// ---------------------------------------------------------------------------
// k_select: pure filter stream. No shared memory, no barriers.
// ---------------------------------------------------------------------------
__device__ __forceinline__ void pushg(int b, int idx, float v) {
    int p = atomicAdd(&g_cnt[b], 1);
    if (p < GCAP) {
        g_cval[(size_t)b * GCAP + p] = v;
        g_cidx[(size_t)b * GCAP + p] = idx;
    }
}

__device__ __forceinline__ void push4(int b, int gi4, float4 a, float thr) {
    int bi = gi4 * 4;
    if (a.x >= thr) pushg(b, bi,     a.x);
    if (a.y >= thr) pushg(b, bi + 1, a.y);
    if (a.z >= thr) pushg(b, bi + 2, a.z);
    if (a.w >= thr) pushg(b, bi + 3, a.w);
}

__global__ __launch_bounds__(256)
void k_select(const float* __restrict__ logits) {
    const int blk = blockIdx.x;
    const int b   = blk / PARTS;
    const int prt = blk % PARTS;
    const float thr = __ldg(&g_thrF[b]);

    const int base4 = prt * CH4;
    const float4* lp4 = reinterpret_cast<const float4*>(logits)
                        + (size_t)b * NPB4 + base4;

    int i = threadIdx.x;
    // paired iterations for MLP=2
    for (; i + 256 < CH4; i += 512) {
        float4 a0 = __ldg(lp4 + i);
        float4 a1 = __ldg(lp4 + i + 256);
        float m0 = fmaxf(fmaxf(a0.x, a0.y), fmaxf(a0.z, a0.w));
        float m1 = fmaxf(fmaxf(a1.x, a1.y), fmaxf(a1.z, a1.w));
        if (fmaxf(m0, m1) >= thr) {           // rare path
            if (m0 >= thr) push4(b, base4 + i,       a0, thr);
            if (m1 >= thr) push4(b, base4 + i + 256, a1, thr);
        }
    }
    if (i < CH4) {
        float4 a0 = __ldg(lp4 + i);
        float m0 = fmaxf(fmaxf(a0.x, a0.y), fmaxf(a0.z, a0.w));
        if (m0 >= thr) push4(b, base4 + i, a0, thr);
    }
}

// ---------------------------------------------------------------------------
// k_final: exact top-K from ~800 candidates per batch.
// ---------------------------------------------------------------------------
__global__ __launch_bounds__(1024)
void k_final(const float* __restrict__ segs,
             const float* __restrict__ sizes,
             float* __restrict__ out) {
    __shared__ unsigned skey[FBUF];
    __shared__ int sidx2[FBUF];
    __shared__ int hist[NBINS];
    __shared__ int sufArr[32];
    __shared__ int s_cnt;
    __shared__ unsigned s_thrKey;

    const int b = blockIdx.x, tid = threadIdx.x;
    int n = g_cnt[b];
    if (n > GCAP) n = GCAP;
    const float* gv = g_cval + (size_t)b * GCAP;
    const int*   gi = g_cidx + (size_t)b * GCAP;

    for (int i = tid; i < NBINS; i += 1024) hist[i] = 0;
    if (tid == 0) s_cnt = 0;
    __syncthreads();
    for (int j = tid; j < n; j += 1024)
        atomicAdd(&hist[fkey(gv[j]) >> 21], 1);
    __syncthreads();
    const int Keff = (n < TOPK) ? n : TOPK;
    if (tid < 32) {
        unsigned tk = warp_find_thr(hist, Keff, sufArr);
        if (tid == 0) s_thrKey = tk;
    }
    __syncthreads();
    const unsigned tk = s_thrKey;
    for (int j = tid; j < n; j += 1024) {
        unsigned k = fkey(gv[j]);
        if (k >= tk) {
            int p = atomicAdd(&s_cnt, 1);
            if (p < FBUF) { skey[p] = k; sidx2[p] = gi[j]; }
        }
    }
    __syncthreads();
    const int m = min(s_cnt, FBUF);
    const float sz = __ldg(sizes + b);

    // Exact ranking: total order (value desc, index asc) matches jax.lax.top_k.
    for (int i = tid; i < m; i += 1024) {
        const unsigned ki = skey[i];
        const int ii = sidx2[i];
        int rank = 0;
        for (int j = 0; j < m; j++) {
            unsigned kj = skey[j];
            rank += (kj > ki) || (kj == ki && sidx2[j] < ii);
        }
        if (rank < TOPK) {
            float v = unkey(ki);
            float score = 1.0f / (1.0f + expf(-v));
            int q = ii / CN;
            int lab = ii - q * CN;
            float2 seg = reinterpret_cast<const float2*>(segs)[(size_t)b * QN + q];
            float t1 = (seg.x - 0.5f * seg.y) * sz;
            float t2 = (seg.x + 0.5f * seg.y) * sz;
            const int BK = BATCH * TOPK;
            int o = b * TOPK + rank;
            out[o]                  = score;       // scores
            out[BK + o]             = (float)lab;  // labels
            out[2 * BK + 2 * o]     = t1;          // segments[...,0]
            out[2 * BK + 2 * o + 1] = t2;          // segments[...,1]
            out[4 * BK + o]         = (float)q;    // query_ids
        }
    }
}

extern "C" void kernel_launch(void* const* d_in, const int* in_sizes, int n_in,
                              void* d_out, int out_size) {
    const float* logits = (const float*)d_in[0];   // [64,2000,200] f32
    const float* segs   = (const float*)d_in[1];   // [64,2000,2]   f32
    const float* sizes  = (const float*)d_in[2];   // [64]          f32
    float* out = (float*)d_out;

    k_thr<<<BATCH, 256>>>(logits);
    k_select<<<BATCH * PARTS, 256>>>(logits);
    k_final<<<BATCH, 1024>>>(segs, sizes, out);
}

// round 4
// speedup vs baseline: 1.0522x; 1.0522x over previous
#include <cuda_runtime.h>
#include <cstdint>
#include <math.h>

// Problem constants
#define BATCH 64
#define QN    2000
#define CN    200
#define NPB   (QN*CN)        // 400000 elements per batch
#define NPB4  (NPB/4)        // 100000 float4 per batch
#define TOPK  100
#define PARTS 20             // blocks per batch -> 64*20 = 1280 blocks of 256 thr
#define CH4   5000           // float4 per chunk (20*5000 = 100000 exactly)
#define GCAP  8192           // per-batch global candidate capacity
#define NBINS 2048           // histogram bins (11-bit prefixes)
#define MCAP  512            // final pruned-survivor buffer

// Global scratch (static device arrays; zero-initialized at module load,
// and reset by the last block of each batch at the end of every run).
__device__ unsigned g_ckey[(size_t)BATCH * GCAP];
__device__ int      g_cidx[(size_t)BATCH * GCAP];
__device__ int      g_cnt[BATCH];
__device__ int      g_done[BATCH];

__device__ __forceinline__ unsigned fkey(float f) {
    unsigned u = __float_as_uint(f);
    return (u & 0x80000000u) ? ~u : (u | 0x80000000u);
}
__device__ __forceinline__ float unkey(unsigned k) {
    unsigned u = (k & 0x80000000u) ? (k ^ 0x80000000u) : ~k;
    return __uint_as_float(u);
}

// ---------------------------------------------------------------------------
// Block-collective (tid<32 active): find max bin g with suffix(g) >= Keff.
// Outputs bin g and rem = Keff - suffix(g+1)  (how many must come from bin g).
// ---------------------------------------------------------------------------
__device__ __forceinline__ void warp_find_bin(const int* hist, int Keff,
                                              volatile int* sufArr,
                                              int* out_g, int* out_rem) {
    const int lane = threadIdx.x & 31;
    int part = 0;
#pragma unroll 8
    for (int i = 0; i < 64; i++) part += hist[lane * 64 + i];
    int s = part;
#pragma unroll
    for (int off = 1; off < 32; off <<= 1) {
        int t = __shfl_down_sync(0xFFFFFFFFu, s, off);
        if (lane + off < 32) s += t;
    }
    sufArr[lane] = s;
    __syncwarp();
    if (lane == 0) {
        int c = 0;
        for (int l = 31; l >= 0; l--) {
            if (sufArr[l] >= Keff) { c = l; break; }
        }
        int above = (c < 31) ? sufArr[c + 1] : 0;   // suffix((c+1)*64)
        int g = c * 64 + 63;
        for (;; --g) {
            above += hist[g];                        // above = suffix(g)
            if (above >= Keff || g == c * 64) break;
        }
        *out_g = g;
        *out_rem = Keff - (above - hist[g]);         // from suffix(g+1)
    }
}

__device__ __forceinline__ void pushg(int b, int idx, float v) {
    int p = atomicAdd(&g_cnt[b], 1);
    if (p < GCAP) {
        g_ckey[(size_t)b * GCAP + p] = fkey(v);
        g_cidx[(size_t)b * GCAP + p] = idx;
    }
}

__device__ __forceinline__ void push4(int b, int ei, float4 a, float thr) {
    if (a.x >= thr) pushg(b, ei,     a.x);
    if (a.y >= thr) pushg(b, ei + 1, a.y);
    if (a.z >= thr) pushg(b, ei + 2, a.z);
    if (a.w >= thr) pushg(b, ei + 3, a.w);
}

__global__ __launch_bounds__(256)
void k_fused(const float* __restrict__ logits,
             const float* __restrict__ segs,
             const float* __restrict__ sizes,
             float* __restrict__ out) {
    __shared__ int hist[NBINS];
    __shared__ int sufArr[32];
    __shared__ unsigned skey[MCAP];
    __shared__ int sidx[MCAP];
    __shared__ int s_cnt, s_last, s_g, s_rem;

    const int blk = blockIdx.x;
    const int b   = blk / PARTS;
    const int prt = blk % PARTS;
    const int tid = threadIdx.x;
    const float4* lp4 = reinterpret_cast<const float4*>(logits)
                        + (size_t)b * NPB4 + (size_t)prt * CH4;
    const float NEG_INF = __int_as_float(0xFF800000);

    // ---- Phase 1: local threshold from a 8192-value sample of this chunk.
    float m = NEG_INF;
#pragma unroll
    for (int k = 0; k < 8; k++) {
        float4 a = __ldg(lp4 + tid + k * 256);   // first 2048 float4 of chunk
        m = fmaxf(m, fmaxf(fmaxf(a.x, a.y), fmaxf(a.z, a.w)));
    }
    const unsigned mykey = fkey(m);
    unsigned thrK = 0;
#pragma unroll
    for (int bit = 31; bit >= 16; --bit) {
        unsigned cand = thrK | (1u << bit);
        if (__syncthreads_count(mykey >= cand) >= 28) thrK = cand;
    }
    const float thr = unkey(thrK);

    // ---- Phase 2: stream whole chunk, filter, push survivors (~68/chunk).
    const int ebase = prt * CH4 * 4;   // batch-relative element base of chunk
    for (int i = tid; i < CH4; i += 1024) {
        const int i1 = i + 256, i2 = i + 512, i3 = i + 768;
        float4 a0 = __ldg(lp4 + i);
        float4 a1 = (i1 < CH4) ? __ldg(lp4 + i1) : make_float4(NEG_INF, NEG_INF, NEG_INF, NEG_INF);
        float4 a2 = (i2 < CH4) ? __ldg(lp4 + i2) : make_float4(NEG_INF, NEG_INF, NEG_INF, NEG_INF);
        float4 a3 = (i3 < CH4) ? __ldg(lp4 + i3) : make_float4(NEG_INF, NEG_INF, NEG_INF, NEG_INF);
        float m0 = fmaxf(fmaxf(a0.x, a0.y), fmaxf(a0.z, a0.w));
        float m1 = fmaxf(fmaxf(a1.x, a1.y), fmaxf(a1.z, a1.w));
        float m2 = fmaxf(fmaxf(a2.x, a2.y), fmaxf(a2.z, a2.w));
        float m3 = fmaxf(fmaxf(a3.x, a3.y), fmaxf(a3.z, a3.w));
        if (fmaxf(fmaxf(m0, m1), fmaxf(m2, m3)) >= thr) {   // rare path
            if (m0 >= thr) push4(b, ebase + i  * 4, a0, thr);
            if (m1 >= thr) push4(b, ebase + i1 * 4, a1, thr);
            if (m2 >= thr) push4(b, ebase + i2 * 4, a2, thr);
            if (m3 >= thr) push4(b, ebase + i3 * 4, a3, thr);
        }
    }

    // ---- Phase 3: last-block ticket for this batch.
    __threadfence();
    __syncthreads();
    if (tid == 0) s_last = (atomicAdd(&g_done[b], 1) == PARTS - 1);
    __syncthreads();
    if (!s_last) return;

    // ---- Phase 4 (one block per batch): exact top-K finish.
    int n = g_cnt[b];
    if (n > GCAP) n = GCAP;
    const unsigned* gk = g_ckey + (size_t)b * GCAP;
    const int*      gi = g_cidx + (size_t)b * GCAP;
    const int Keff = (n < TOPK) ? n : TOPK;

    // 4a: histogram over top 11 key bits -> bin g, rem needed from bin g.
    for (int i = tid; i < NBINS; i += 256) hist[i] = 0;
    __syncthreads();
    for (int j = tid; j < n; j += 256) atomicAdd(&hist[gk[j] >> 21], 1);
    __syncthreads();
    if (tid < 32) warp_find_bin(hist, Keff, sufArr, &s_g, &s_rem);
    __syncthreads();
    const unsigned g1 = (unsigned)s_g;
    const int rem = s_rem;

    // 4b: refine within bin g using the next 11 bits -> 22-bit threshold.
    for (int i = tid; i < NBINS; i += 256) hist[i] = 0;
    __syncthreads();
    for (int j = tid; j < n; j += 256) {
        unsigned k = gk[j];
        if ((k >> 21) == g1) atomicAdd(&hist[(k >> 10) & 2047], 1);
    }
    __syncthreads();
    if (tid < 32) warp_find_bin(hist, rem, sufArr, &s_g, &s_rem);
    if (tid == 0) s_cnt = 0;
    __syncthreads();
    const unsigned TK = (g1 << 21) | ((unsigned)s_g << 10);

    // 4c: collect m ~ 100-110 finalists into shared memory.
    for (int j = tid; j < n; j += 256) {
        unsigned k = gk[j];
        if (k >= TK) {
            int p = atomicAdd(&s_cnt, 1);
            if (p < MCAP) { skey[p] = k; sidx[p] = gi[j]; }
        }
    }
    __syncthreads();
    const int mm = min(s_cnt, MCAP);
    const float sz = __ldg(sizes + b);

    // 4d: exact ranking (value desc, index asc — matches jax.lax.top_k).
    for (int i = tid; i < mm; i += 256) {
        const unsigned ki = skey[i];
        const int ii = sidx[i];
        int rank = 0;
        for (int j = 0; j < mm; j++) {
            unsigned kj = skey[j];
            rank += (kj > ki) || (kj == ki && sidx[j] < ii);
        }
        if (rank < TOPK) {
            float v = unkey(ki);
            float score = 1.0f / (1.0f + expf(-v));
            int q = ii / CN;
            int lab = ii - q * CN;
            float2 seg = reinterpret_cast<const float2*>(segs)[(size_t)b * QN + q];
            float t1 = (seg.x - 0.5f * seg.y) * sz;
            float t2 = (seg.x + 0.5f * seg.y) * sz;
            const int BK = BATCH * TOPK;
            int o = b * TOPK + rank;
            out[o]                  = score;       // scores
            out[BK + o]             = (float)lab;  // labels
            out[2 * BK + 2 * o]     = t1;          // segments[...,0]
            out[2 * BK + 2 * o + 1] = t2;          // segments[...,1]
            out[4 * BK + o]         = (float)q;    // query_ids
        }
    }

    // ---- Phase 5: reset counters for the next graph replay.
    __syncthreads();
    if (tid == 0) { g_cnt[b] = 0; g_done[b] = 0; }
}

extern "C" void kernel_launch(void* const* d_in, const int* in_sizes, int n_in,
                              void* d_out, int out_size) {
    const float* logits = (const float*)d_in[0];   // [64,2000,200] f32
    const float* segs   = (const float*)d_in[1];   // [64,2000,2]   f32
    const float* sizes  = (const float*)d_in[2];   // [64]          f32
    float* out = (float*)d_out;

    k_fused<<<BATCH * PARTS, 256>>>(logits, segs, sizes, out);
}